// round 12
// baseline (speedup 1.0000x reference)
#include <cuda_runtime.h>
#include <cuda_fp16.h>
#include <cstdint>

// ---------------------------------------------------------------------------
// EncoderByType (GB300, compute_103): fp16 m16n8k16 mma.sync GEMM.
// Round 12: CTA 256x128x64, 8 warps (4m x 2n), warp tile 64x64 ->
// smem traffic 176KB/kt < tensor 2048cyc/kt (tensor-bound at last).
// 4-stage cp.async ring (192KB, CP_WAIT(2)) + fragment double-buffering.
// 1 CTA/SM. fp16 activations padded to 256-row tiles.
// ---------------------------------------------------------------------------

__device__ __half g_x [32262144];          // padded fp16 inputs (zero-init)
__device__ __half g_h1[240384ll * 512];
__device__ __half g_h2[240384ll * 512];
__device__ __half g_Wt[1409024];           // 9 weights, [N,K] fp16

// ------------------------- helpers -----------------------------------------
__device__ __forceinline__ uint32_t smem_u32(const void* p) {
    uint32_t a;
    asm("{ .reg .u64 t; cvta.to.shared.u64 t, %1; cvt.u32.u64 %0, t; }"
        : "=r"(a) : "l"(p));
    return a;
}
__device__ __forceinline__ float fast_sigmoid(float x) {
    float t;
    asm("tanh.approx.f32 %0, %1;" : "=f"(t) : "f"(0.5f * x));
    return fmaf(0.5f, t, 0.5f);
}
__device__ __forceinline__ uint32_t packh2(float lo, float hi) {
    __half2 h = __floats2half2_rn(lo, hi);
    return *reinterpret_cast<uint32_t*>(&h);
}
__device__ __forceinline__ void mma_fp16(float* d, const uint4& a,
                                         uint32_t b0, uint32_t b1) {
    asm volatile(
        "mma.sync.aligned.m16n8k16.row.col.f32.f16.f16.f32 "
        "{%0,%1,%2,%3}, {%4,%5,%6,%7}, {%8,%9}, {%0,%1,%2,%3};"
        : "+f"(d[0]), "+f"(d[1]), "+f"(d[2]), "+f"(d[3])
        : "r"(a.x), "r"(a.y), "r"(a.z), "r"(a.w), "r"(b0), "r"(b1));
}
__device__ __forceinline__ void ldsm4(uint4& d, uint32_t addr) {
    asm volatile(
        "ldmatrix.sync.aligned.m8n8.x4.shared.b16 {%0,%1,%2,%3}, [%4];"
        : "=r"(d.x), "=r"(d.y), "=r"(d.z), "=r"(d.w) : "r"(addr));
}
#define CP_ASYNC16(dst, src) \
    asm volatile("cp.async.cg.shared.global [%0], [%1], 16;" :: "r"(dst), "l"(src))
#define CP_COMMIT() asm volatile("cp.async.commit_group;" ::: "memory")
#define CP_WAIT(n)  asm volatile("cp.async.wait_group %0;" :: "n"(n) : "memory")

// ------------------------- weight transpose+convert ------------------------
struct TransArgs {
    const float* W[9];
    long long wtoff[9];
    int K[9];
    int N[9];
    int tbase[10];
};

__global__ void __launch_bounds__(256)
transpose_weights(TransArgs a) {
    int m = 0;
    while ((int)blockIdx.x >= a.tbase[m + 1]) m++;
    int t = blockIdx.x - a.tbase[m];
    int Km = a.K[m], Nm = a.N[m];
    int tilesN = Nm >> 5;
    int tk = t / tilesN, tn = t % tilesN;

    __shared__ float tile[32][33];
    int tx = threadIdx.x & 31, ty0 = threadIdx.x >> 5;
    const float* W = a.W[m];
#pragma unroll
    for (int i = 0; i < 4; i++) {
        int ty = ty0 + i * 8;
        tile[ty][tx] = W[(long long)(tk * 32 + ty) * Nm + tn * 32 + tx];
    }
    __syncthreads();
    __half* Wt = g_Wt + a.wtoff[m];
#pragma unroll
    for (int i = 0; i < 4; i++) {
        int ty = ty0 + i * 8;
        Wt[(long long)(tn * 32 + ty) * Km + tk * 32 + tx] = __float2half(tile[tx][ty]);
    }
}

// ------------------------- input convert (all 3 in one launch) -------------
__global__ void __launch_bounds__(256)
cvt_all(const float* s0, const float* s1, const float* s2,
        __half* d0, __half* d1, __half* d2, int c1, int c2, int c3)
{
    int i = blockIdx.x * 256 + threadIdx.x;
    if (i >= c3) return;
    const float* s;
    __half* d;
    int j;
    if (i < c1)      { s = s0; d = d0; j = i; }
    else if (i < c2) { s = s1; d = d1; j = i - c1; }
    else             { s = s2; d = d2; j = i - c2; }
    float4 v = ((const float4*)s)[j];
    uint2 o;
    o.x = packh2(v.x, v.y);
    o.y = packh2(v.z, v.w);
    ((uint2*)d)[j] = o;
}

// ------------------------- fused layer kernel ------------------------------
// Grid: (N/128, sum 256-row tiles). 256 threads = 8 warps (4m x 2n),
// warp tile 64x64. Stage = A(256x128B=32KB) + B(128x128B=16KB) = 48KB;
// 4 stages = 192KB. BK=64 halfs. XOR swizzle: chunk c at c ^ (row & 7).
struct LArgs {
    const __half* A[3];
    void* C[3];
    const float* bias[3];
    const __half* Wt[3];
    int M[3], K[3];
    int tb[4];
    int N;
};

#define STG_SZ 49152u

template <bool CF32>
__global__ void __launch_bounds__(256, 1)
mlp_layer(LArgs a)
{
    extern __shared__ char smem[];
    const int t = ((int)blockIdx.y >= a.tb[1]) + ((int)blockIdx.y >= a.tb[2]);
    const int K = a.K[t];
    const int N = a.N;
    const long long bm = (long long)((int)blockIdx.y - a.tb[t]) * 256;
    const int bn = blockIdx.x * 128;
    const __half* Ah = a.A[t];
    const __half* Wt = a.Wt[t];
    const int KT = K >> 6;

    const int tid = threadIdx.x;
    const int lane = tid & 31;
    const int wid = tid >> 5;
    const int warp_m = wid & 3;     // 4 m-warps of 64 rows
    const int warp_n = wid >> 2;    // 2 n-warps of 64 cols

    const uint32_t sb = smem_u32(smem);

    // ---- cp.async maps ----
    const int crow = tid >> 3;          // 0..31
    const int cchk = tid & 7;
    const __half* pA = Ah + (bm + crow) * (long long)K + cchk * 8;
    const __half* pB = Wt + (long long)(bn + crow) * K + cchk * 8;
    const uint32_t swz = (uint32_t)((cchk ^ (crow & 7)) * 16);
    const uint32_t dA = sb + crow * 128 + swz;
    const uint32_t dB = sb + 32768 + crow * 128 + swz;
    const long long rstep = 32ll * K;   // halfs per 32 rows

    // ---- ldmatrix address bases (offsets within a stage) ----
    const int l15 = lane & 15;
    const int ahi = lane >> 4;
    const uint32_t aX = (uint32_t)(lane & 7);
    const uint32_t aOff = (uint32_t)(warp_m * 64 + l15) * 128;
    const int bn_l = warp_n * 64 + ((lane >> 4) << 3) + (lane & 7);
    const int bhi = (lane >> 3) & 1;
    const uint32_t bOff = 32768u + (uint32_t)bn_l * 128;

    float acc[4][8][4];
#pragma unroll
    for (int i = 0; i < 4; i++)
#pragma unroll
        for (int j = 0; j < 8; j++)
#pragma unroll
            for (int q = 0; q < 4; q++) acc[i][j][q] = 0.0f;

    uint4 afr[2][4], bfr[2][4];

#define ISSUE(kt, slot)                                                      \
    do {                                                                     \
        const __half* sA_ = pA + (kt) * 64;                                  \
        const __half* sB_ = pB + (kt) * 64;                                  \
        uint32_t oA_ = dA + (slot) * STG_SZ;                                 \
        uint32_t oB_ = dB + (slot) * STG_SZ;                                 \
        _Pragma("unroll")                                                    \
        for (int i = 0; i < 8; i++)                                          \
            CP_ASYNC16(oA_ + i * 4096u, sA_ + i * rstep);                    \
        _Pragma("unroll")                                                    \
        for (int i = 0; i < 4; i++)                                          \
            CP_ASYNC16(oB_ + i * 4096u, sB_ + i * rstep);                    \
    } while (0)

#define LOAD_FRAGS(stg_, s_, pb_)                                            \
    do {                                                                     \
        _Pragma("unroll")                                                    \
        for (int mt = 0; mt < 4; mt++)                                       \
            ldsm4(afr[pb_][mt], (stg_) + aOff + mt * 2048u +                 \
                  ((((uint32_t)(2 * (s_) + ahi)) ^ aX) << 4));               \
        _Pragma("unroll")                                                    \
        for (int ng = 0; ng < 4; ng++)                                       \
            ldsm4(bfr[pb_][ng], (stg_) + bOff + ng * 2048u +                 \
                  ((((uint32_t)(2 * (s_) + bhi)) ^ aX) << 4));               \
    } while (0)

    // ---- prologue: fill up to 3 stages ----
    ISSUE(0, 0);
    CP_COMMIT();
    if (1 < KT) ISSUE(1, 1);
    CP_COMMIT();
    if (2 < KT) ISSUE(2, 2);
    CP_COMMIT();

    CP_WAIT(2);
    __syncthreads();
    uint32_t stg = sb;
    LOAD_FRAGS(stg, 0, 0);

    for (int kt = 0; kt < KT; kt++) {
        if (kt + 3 < KT) {
            ISSUE(kt + 3, (kt + 3) & 3);
        }
        CP_COMMIT();

#pragma unroll
        for (int s = 0; s < 4; s++) {
            const int cb = s & 1;
            if (s < 3) LOAD_FRAGS(stg, s + 1, cb ^ 1);
#pragma unroll
            for (int mt = 0; mt < 4; mt++)
#pragma unroll
                for (int ng = 0; ng < 4; ng++) {
                    mma_fp16(acc[mt][2 * ng],     afr[cb][mt], bfr[cb][ng].x, bfr[cb][ng].y);
                    mma_fp16(acc[mt][2 * ng + 1], afr[cb][mt], bfr[cb][ng].z, bfr[cb][ng].w);
                }
        }
        if (kt + 1 < KT) {
            CP_WAIT(2);
            __syncthreads();
            stg = sb + (uint32_t)((kt + 1) & 3) * STG_SZ;
            LOAD_FRAGS(stg, 0, 0);
        }
    }
#undef ISSUE
#undef LOAD_FRAGS

    // ---- epilogue: bias + sigmoid ----
    const float* bias = a.bias[t];
    const int M = a.M[t];
#pragma unroll
    for (int mt = 0; mt < 4; mt++) {
        long long r0 = bm + warp_m * 64 + mt * 16 + (lane >> 2);
        long long r1 = r0 + 8;
#pragma unroll
        for (int np = 0; np < 8; np++) {
            int n = bn + warp_n * 64 + np * 8 + 2 * (lane & 3);
            float2 bv = *(const float2*)(bias + n);
            float* d = acc[mt][np];
            float s0 = fast_sigmoid(d[0] + bv.x);
            float s1 = fast_sigmoid(d[1] + bv.y);
            float s2 = fast_sigmoid(d[2] + bv.x);
            float s3 = fast_sigmoid(d[3] + bv.y);
            if (CF32) {
                float* C = (float*)a.C[t];
                if (r0 < M) *(float2*)(C + r0 * N + n) = make_float2(s0, s1);
                if (r1 < M) *(float2*)(C + r1 * N + n) = make_float2(s2, s3);
            } else {
                __half* C = (__half*)a.C[t];
                *(uint32_t*)(C + r0 * N + n) = packh2(s0, s1);
                *(uint32_t*)(C + r1 * N + n) = packh2(s2, s3);
            }
        }
    }
}

// ------------------------- host launcher -----------------------------------
extern "C" void kernel_launch(void* const* d_in, const int* in_sizes, int n_in,
                              void* d_out, int out_size)
{
    (void)n_in; (void)out_size;
    const int din[3] = {64, 128, 256};
    int n[3];
    for (int t = 0; t < 3; t++) n[t] = in_sizes[t] / din[t];

    int tiles[3], tb[4];
    tb[0] = 0;
    for (int t = 0; t < 3; t++) {
        tiles[t] = (n[t] + 255) / 256;
        tb[t + 1] = tb[t] + tiles[t];
    }
    long long padrows[3] = {(long long)tiles[0] * 256, (long long)tiles[1] * 256,
                            (long long)tiles[2] * 256};
    long long hb[3] = {0, padrows[0], padrows[0] + padrows[1]};
    long long xoff[3] = {0, padrows[0] * din[0],
                         padrows[0] * din[0] + padrows[1] * din[1]};
    long long outbase[3] = {0, n[0], (long long)n[0] + n[1]};

    const int SMEM = 4 * 49152;   // 196608
    static int attr_done = 0;
    if (!attr_done) {
        cudaFuncSetAttribute(mlp_layer<false>,
                             cudaFuncAttributeMaxDynamicSharedMemorySize, SMEM);
        cudaFuncSetAttribute(mlp_layer<true>,
                             cudaFuncAttributeMaxDynamicSharedMemorySize, SMEM);
        attr_done = 1;
    }

    // ---- transpose + fp16-convert all weights ----
    TransArgs ta;
    long long woff[9];
    {
        long long w = 0;
        int tbt = 0;
        for (int t = 0; t < 3; t++) {
            int Ks[3] = {din[t], 512, 512};
            int Ns[3] = {512, 512, 256};
            for (int l = 0; l < 3; l++) {
                int idx = t * 3 + l;
                ta.W[idx] = (const float*)d_in[4 + 6 * t + 2 * l];
                ta.wtoff[idx] = w;
                woff[idx] = w;
                ta.K[idx] = Ks[l];
                ta.N[idx] = Ns[l];
                ta.tbase[idx] = tbt;
                tbt += (Ks[l] / 32) * (Ns[l] / 32);
                w += (long long)Ks[l] * Ns[l];
            }
        }
        ta.tbase[9] = tbt;
        transpose_weights<<<tbt, 256>>>(ta);
    }

    __half *xh, *h1, *h2, *wt;
    cudaGetSymbolAddress((void**)&xh, g_x);
    cudaGetSymbolAddress((void**)&h1, g_h1);
    cudaGetSymbolAddress((void**)&h2, g_h2);
    cudaGetSymbolAddress((void**)&wt, g_Wt);

    // ---- convert inputs to padded fp16 (one launch) ----
    {
        int c1 = n[0] * din[0] / 4;
        int c2 = c1 + n[1] * din[1] / 4;
        int c3 = c2 + n[2] * din[2] / 4;
        cvt_all<<<(c3 + 255) / 256, 256>>>(
            (const float*)d_in[0], (const float*)d_in[1], (const float*)d_in[2],
            xh + xoff[0], xh + xoff[1], xh + xoff[2], c1, c2, c3);
    }

    // ---- layer launches ----
    LArgs a;
    for (int i = 0; i < 4; i++) a.tb[i] = tb[i];

    a.N = 512;
    for (int t = 0; t < 3; t++) {
        a.A[t] = xh + xoff[t];
        a.C[t] = h1 + hb[t] * 512;
        a.bias[t] = (const float*)d_in[5 + 6 * t];
        a.Wt[t] = wt + woff[t * 3 + 0];
        a.M[t] = n[t];
        a.K[t] = din[t];
    }
    mlp_layer<false><<<dim3(4, tb[3]), 256, SMEM>>>(a);

    for (int t = 0; t < 3; t++) {
        a.A[t] = h1 + hb[t] * 512;
        a.C[t] = h2 + hb[t] * 512;
        a.bias[t] = (const float*)d_in[7 + 6 * t];
        a.Wt[t] = wt + woff[t * 3 + 1];
        a.M[t] = n[t];
        a.K[t] = 512;
    }
    mlp_layer<false><<<dim3(4, tb[3]), 256, SMEM>>>(a);

    a.N = 256;
    for (int t = 0; t < 3; t++) {
        a.A[t] = h2 + hb[t] * 512;
        a.C[t] = (float*)d_out + outbase[t] * 256;
        a.bias[t] = (const float*)d_in[9 + 6 * t];
        a.Wt[t] = wt + woff[t * 3 + 2];
        a.M[t] = n[t];
        a.K[t] = 512;
    }
    mlp_layer<true><<<dim3(2, tb[3]), 256, SMEM>>>(a);
}